// round 7
// baseline (speedup 1.0000x reference)
#include <cuda_runtime.h>
#include <cuda_fp16.h>

#define NN 100000
#define EE 1600000
#define NCHUNK 128
#define CH 782   // ceil(100000/128)

// ---------------- scratch (static device globals) ----------------------------
__device__ uint2 g_hp1v[NN * 16];          // fp16 features, 64ch/node (uint2 = 4ch)
__device__ float g_out1[NN * 64];
__device__ float g_as1[NN * 4];
__device__ float g_ad1[NN * 4];
__device__ float g_asum1[NN * 4];
__device__ uint2 g_hp2v[NN * 16];
__device__ float g_out2[NN * 64];
__device__ float g_as2[NN];
__device__ float g_ad2[NN];
__device__ float g_asum2[NN];
__device__ uint2 g_EAv[NN * 16];           // fp16 EA
__device__ float g_EB[NN * 64];
// rank-2 encoder precompute
__device__ float g_P0[64], g_P1[64], g_Pb[64];
// CSR build
__device__ int  g_cnt[NN];                 // zero-initialized; re-zeroed each launch
__device__ int  g_offs[NN + 1];
__device__ int  g_cur[NN];
__device__ int2 g_csr[EE];                 // .x = src node, .y = edge id
__device__ int  g_boff[NCHUNK];

// ---------------- helpers ----------------------------------------------------
__device__ __forceinline__ float lrelu(float x, float s) { return x > 0.f ? x : s * x; }
__device__ __forceinline__ float tanha(float x) {
    float r; asm("tanh.approx.f32 %0, %1;" : "=f"(r) : "f"(x)); return r;
}

typedef unsigned long long ull;
__device__ __forceinline__ ull pack2(float v) {
    ull r;
    unsigned int u = __float_as_uint(v);
    asm("mov.b64 %0, {%1, %1};" : "=l"(r) : "r"(u));
    return r;
}
__device__ __forceinline__ void fma2(ull& d, ull a, ull b) {
    asm("fma.rn.f32x2 %0, %1, %2, %3;" : "=l"(d) : "l"(a), "l"(b), "l"(d));
}
__device__ __forceinline__ float2 unpack2(ull v) {
    unsigned int lo, hi;
    asm("mov.b64 {%0, %1}, %2;" : "=r"(lo), "=r"(hi) : "l"(v));
    return make_float2(__uint_as_float(lo), __uint_as_float(hi));
}
__device__ __forceinline__ unsigned int h2bits(float a, float b) {
    __half2 h = __floats2half2_rn(a, b);
    return *(unsigned int*)&h;
}
__device__ __forceinline__ float2 h2f2(unsigned int b) {
    return __half22float2(*(__half2*)&b);
}

// ==================== CSR build ==============================================
__global__ void k_hist(const int* __restrict__ dst, int e) {
    int t = blockIdx.x * blockDim.x + threadIdx.x;
    if (t < e) atomicAdd(&g_cnt[dst[t]], 1);
}
// one block: per-chunk totals (8 threads/chunk) + scan over 128 chunks
__global__ void k_sumscan(int n) {
    __shared__ int ssum[NCHUNK];
    int t = threadIdx.x;                   // 1024
    int chunk = t >> 3, sub = t & 7;
    int base = chunk * CH;
    int s = 0;
    for (int i = sub; i < CH; i += 8) {
        int idx = base + i;
        if (idx < n) s += g_cnt[idx];
    }
    s += __shfl_xor_sync(0xffffffffu, s, 1);
    s += __shfl_xor_sync(0xffffffffu, s, 2);
    s += __shfl_xor_sync(0xffffffffu, s, 4);
    if (sub == 0) ssum[chunk] = s;
    __syncthreads();
    int tot = (t < NCHUNK) ? ssum[t] : 0;
    for (int o = 1; o < NCHUNK; o <<= 1) {
        int x = (t < NCHUNK && t >= o) ? ssum[t - o] : 0;
        __syncthreads();
        if (t < NCHUNK) ssum[t] += x;
        __syncthreads();
    }
    if (t < NCHUNK) g_boff[t] = ssum[t] - tot;   // exclusive
}
__global__ void k_scanwrite(int n) {
    __shared__ int sd[1024];
    int b = blockIdx.x, t = threadIdx.x;
    int base = b * CH;
    int v = (t < CH && base + t < n) ? g_cnt[base + t] : 0;
    sd[t] = v; __syncthreads();
    for (int o = 1; o < 1024; o <<= 1) {
        int x = (t >= o) ? sd[t - o] : 0;
        __syncthreads();
        sd[t] += x;
        __syncthreads();
    }
    int excl = sd[t] - v + g_boff[b];
    if (t < CH && base + t < n) {
        g_offs[base + t] = excl;
        g_cur[base + t] = excl;
        g_cnt[base + t] = 0;               // re-zero for next launch (graph replay)
    }
    if (base + t == n - 1) g_offs[n] = excl + v;
}
__global__ void k_scatter(const int* __restrict__ src, const int* __restrict__ dst, int e) {
    int t = blockIdx.x * blockDim.x + threadIdx.x;
    if (t >= e) return;
    int d = dst[t];
    int pos = atomicAdd(&g_cur[d], 1);
    g_csr[pos] = make_int2(src[t], t);
}

// ==================== kernel: rank-2 encoder precompute ======================
__global__ void k_pre(const float* __restrict__ encW, const float* __restrict__ encb,
                      const float* __restrict__ g1W) {
    int c = threadIdx.x;           // 64 threads
    float p0 = 0.f, p1 = 0.f, pb = 0.f;
    for (int k = 0; k < 64; k++) {
        float w = g1W[k * 64 + c];
        p0 = fmaf(encW[k], w, p0);
        p1 = fmaf(encW[64 + k], w, p1);
        pb = fmaf(encb[k], w, pb);
    }
    g_P0[c] = p0; g_P1[c] = p1; g_Pb[c] = pb;
}

// ==================== kernel: encoder+gat1 projection (rank-2) ===============
__global__ void k_enc_gat1(const float* __restrict__ x,
                           const float* __restrict__ g1as, const float* __restrict__ g1ad,
                           int n) {
    __shared__ __align__(16) float sP0[64], sP1[64], sPb[64], sAs[64], sAd[64];
    if (threadIdx.x < 64) {
        sP0[threadIdx.x] = g_P0[threadIdx.x];
        sP1[threadIdx.x] = g_P1[threadIdx.x];
        sPb[threadIdx.x] = g_Pb[threadIdx.x];
        sAs[threadIdx.x] = g1as[threadIdx.x];
        sAd[threadIdx.x] = g1ad[threadIdx.x];
    }
    __syncthreads();
    int node = blockIdx.x * blockDim.x + threadIdx.x;
    if (node >= n) return;

    float2 xv = *(const float2*)&x[node * 2];
    float hp[64];
    float asv[4] = {0, 0, 0, 0}, adv[4] = {0, 0, 0, 0};
#pragma unroll
    for (int c = 0; c < 64; c++) {
        float v = fmaf(xv.x, sP0[c], fmaf(xv.y, sP1[c], sPb[c]));
        hp[c] = v;
        asv[c >> 4] = fmaf(v, sAs[c], asv[c >> 4]);
        adv[c >> 4] = fmaf(v, sAd[c], adv[c >> 4]);
    }
    float es[4];
#pragma unroll
    for (int h = 0; h < 4; h++) {
        g_as1[node * 4 + h] = asv[h];
        g_ad1[node * 4 + h] = adv[h];
        es[h] = __expf(lrelu(asv[h] + adv[h], 0.2f));
    }
    *(float4*)&g_asum1[node * 4] = make_float4(es[0], es[1], es[2], es[3]);
#pragma unroll
    for (int q = 0; q < 8; q++) {
        int c = q * 8;
        uint4 u = make_uint4(h2bits(hp[c], hp[c + 1]), h2bits(hp[c + 2], hp[c + 3]),
                             h2bits(hp[c + 4], hp[c + 5]), h2bits(hp[c + 6], hp[c + 7]));
        *(uint4*)&g_hp1v[node * 16 + q * 2] = u;
        float e0 = es[c >> 4];
        *(float4*)&g_out1[node * 64 + c] =
            make_float4(hp[c] * e0, hp[c + 1] * e0, hp[c + 2] * e0, hp[c + 3] * e0);
        *(float4*)&g_out1[node * 64 + c + 4] =
            make_float4(hp[c + 4] * e0, hp[c + 5] * e0, hp[c + 6] * e0, hp[c + 7] * e0);
    }
}

// ==================== kernel: gat1 gather (16 lanes/node, 2 nodes/warp) ======
__global__ void k_msg1(int n) {
    int grp = (blockIdx.x * blockDim.x + threadIdx.x) >> 4;
    if (grp >= n) return;
    int node = grp;
    int lh = threadIdx.x & 15;
    unsigned gbase = threadIdx.x & 16;        // 0 or 16
    unsigned mask = 0xFFFFu << gbase;
    int beg = g_offs[node], end = g_offs[node + 1];

    float adh = g_ad1[node * 4 + (lh & 3)];
    float4 acc = *(const float4*)&g_out1[node * 64 + lh * 4];  // self seed
    float wsum = 0.f;

    for (int i = beg; i < end; i += 4) {
        int idx = i + (lh >> 2);               // 4 edges, 4 lanes (heads) each
        int2 ce = (idx < end) ? g_csr[idx] : make_int2(0, 0);
        float a = g_as1[ce.x * 4 + (lh & 3)] + adh;
        float w = (idx < end) ? __expf(lrelu(a, 0.2f)) : 0.f;
        wsum += w;
#pragma unroll
        for (int k = 0; k < 4; k++) {
            if (i + k >= end) break;
            int   src = __shfl_sync(mask, ce.x, gbase + k * 4);
            float wl  = __shfl_sync(mask, w, gbase + k * 4 + (lh >> 2)); // head = lh>>2
            uint2 hb = g_hp1v[src * 16 + lh];
            float2 v0 = h2f2(hb.x), v1 = h2f2(hb.y);
            acc.x = fmaf(wl, v0.x, acc.x);
            acc.y = fmaf(wl, v0.y, acc.y);
            acc.z = fmaf(wl, v1.x, acc.z);
            acc.w = fmaf(wl, v1.y, acc.w);
        }
    }
    *(float4*)&g_out1[node * 64 + lh * 4] = acc;
    wsum += __shfl_xor_sync(mask, wsum, 4);
    wsum += __shfl_xor_sync(mask, wsum, 8);
    if (lh < 4) g_asum1[node * 4 + lh] += wsum;
}

// ==================== kernel: finish gat1 + gat2 projection (FFMA2) ==========
__global__ void k_fin1_gat2(const float* __restrict__ g1b,
                            const float* __restrict__ g2W,
                            const float* __restrict__ g2as, const float* __restrict__ g2ad,
                            int n) {
    __shared__ __align__(16) float sW[64 * 64];
    __shared__ __align__(16) float sB[64], sAs[64], sAd[64];
    for (int i = threadIdx.x; i < 4096; i += blockDim.x) sW[i] = g2W[i];
    if (threadIdx.x < 64) {
        sB[threadIdx.x] = g1b[threadIdx.x];
        sAs[threadIdx.x] = g2as[threadIdx.x];
        sAd[threadIdx.x] = g2ad[threadIdx.x];
    }
    __syncthreads();
    int node = blockIdx.x * blockDim.x + threadIdx.x;
    if (node >= n) return;

    float inv[4];
#pragma unroll
    for (int h = 0; h < 4; h++) inv[h] = 1.0f / g_asum1[node * 4 + h];

    ull acc[32];
#pragma unroll
    for (int i = 0; i < 32; i++) acc[i] = 0ULL;
#pragma unroll 2
    for (int k4 = 0; k4 < 16; k4++) {
        float4 o = *(const float4*)&g_out1[node * 64 + k4 * 4];
        float iv = inv[k4 >> 2];
        float hv4[4];
        hv4[0] = o.x * iv + sB[k4 * 4];
        hv4[1] = o.y * iv + sB[k4 * 4 + 1];
        hv4[2] = o.z * iv + sB[k4 * 4 + 2];
        hv4[3] = o.w * iv + sB[k4 * 4 + 3];
#pragma unroll
        for (int j = 0; j < 4; j++) {
            float hj = hv4[j] > 0.f ? hv4[j] : expm1f(hv4[j]);
            ull hv = pack2(hj);
            const ulonglong2* wr = (const ulonglong2*)&sW[(k4 * 4 + j) * 64];
#pragma unroll
            for (int c8 = 0; c8 < 16; c8++) {
                ulonglong2 w = wr[c8];
                fma2(acc[2 * c8], hv, w.x);
                fma2(acc[2 * c8 + 1], hv, w.y);
            }
        }
    }
    float hp[64];
#pragma unroll
    for (int i = 0; i < 32; i++) {
        float2 f = unpack2(acc[i]);
        hp[2 * i] = f.x; hp[2 * i + 1] = f.y;
    }
    float as = 0.f, ad = 0.f;
#pragma unroll
    for (int c = 0; c < 64; c++) {
        as = fmaf(hp[c], sAs[c], as);
        ad = fmaf(hp[c], sAd[c], ad);
    }
    g_as2[node] = as;
    g_ad2[node] = ad;
    float es = __expf(lrelu(as + ad, 0.2f));
    g_asum2[node] = es;
#pragma unroll
    for (int q = 0; q < 8; q++) {
        int c = q * 8;
        uint4 u = make_uint4(h2bits(hp[c], hp[c + 1]), h2bits(hp[c + 2], hp[c + 3]),
                             h2bits(hp[c + 4], hp[c + 5]), h2bits(hp[c + 6], hp[c + 7]));
        *(uint4*)&g_hp2v[node * 16 + q * 2] = u;
        *(float4*)&g_out2[node * 64 + c] =
            make_float4(hp[c] * es, hp[c + 1] * es, hp[c + 2] * es, hp[c + 3] * es);
        *(float4*)&g_out2[node * 64 + c + 4] =
            make_float4(hp[c + 4] * es, hp[c + 5] * es, hp[c + 6] * es, hp[c + 7] * es);
    }
}

// ==================== kernel: gat2 gather (16 lanes/node, 2 nodes/warp) ======
__global__ void k_msg2(int n) {
    int grp = (blockIdx.x * blockDim.x + threadIdx.x) >> 4;
    if (grp >= n) return;
    int node = grp;
    int lh = threadIdx.x & 15;
    unsigned gbase = threadIdx.x & 16;
    unsigned mask = 0xFFFFu << gbase;
    int beg = g_offs[node], end = g_offs[node + 1];

    float ad2 = g_ad2[node];
    float4 acc = *(const float4*)&g_out2[node * 64 + lh * 4];
    float wsum = 0.f;

    for (int i = beg; i < end; i += 4) {
        int idx = i + (lh >> 2);
        int2 ce = (idx < end) ? g_csr[idx] : make_int2(0, 0);
        float a = g_as2[ce.x] + ad2;                  // 4 dup lanes broadcast
        float w = (idx < end) ? __expf(lrelu(a, 0.2f)) : 0.f;
        if ((lh & 3) == 0) wsum += w;
#pragma unroll
        for (int k = 0; k < 4; k++) {
            if (i + k >= end) break;
            int   src = __shfl_sync(mask, ce.x, gbase + k * 4);
            float wl  = __shfl_sync(mask, w, gbase + k * 4);
            uint2 hb = g_hp2v[src * 16 + lh];
            float2 v0 = h2f2(hb.x), v1 = h2f2(hb.y);
            acc.x = fmaf(wl, v0.x, acc.x);
            acc.y = fmaf(wl, v0.y, acc.y);
            acc.z = fmaf(wl, v1.x, acc.z);
            acc.w = fmaf(wl, v1.y, acc.w);
        }
    }
    *(float4*)&g_out2[node * 64 + lh * 4] = acc;
    wsum += __shfl_xor_sync(mask, wsum, 4);
    wsum += __shfl_xor_sync(mask, wsum, 8);
    if (lh == 0) g_asum2[node] += wsum;
}

// ==================== kernel: finish gat2 + EA/EB + node head (FFMA2) ========
__global__ void k_fin2_heads(const float* __restrict__ g2b,
                             const float* __restrict__ eoW1, const float* __restrict__ eob1,
                             const float* __restrict__ noW1, const float* __restrict__ nob1,
                             const float* __restrict__ noW2, const float* __restrict__ nob2,
                             float* __restrict__ out, int n, int e) {
    __shared__ __align__(16) float sWa[64 * 64];
    __shared__ __align__(16) float sWb[64 * 64];
    __shared__ __align__(16) float sWn[64 * 64];
    __shared__ __align__(16) float sB[64], sB1[64], sBn[64], sW2[128];
    for (int i = threadIdx.x; i < 4096; i += blockDim.x) {
        sWa[i] = eoW1[i];
        sWb[i] = eoW1[4096 + i];
        sWn[i] = noW1[i];
    }
    if (threadIdx.x < 64) {
        sB[threadIdx.x]  = g2b[threadIdx.x];
        sB1[threadIdx.x] = eob1[threadIdx.x];
        sBn[threadIdx.x] = nob1[threadIdx.x];
    }
    if (threadIdx.x < 128) sW2[threadIdx.x] = noW2[threadIdx.x];
    __syncthreads();
    int node = blockIdx.x * blockDim.x + threadIdx.x;
    if (node >= n) return;

    float inv = 1.0f / g_asum2[node];
    float h2[64];
#pragma unroll
    for (int c4 = 0; c4 < 16; c4++) {
        float4 o = *(const float4*)&g_out2[node * 64 + c4 * 4];
        h2[c4 * 4]     = o.x * inv + sB[c4 * 4];
        h2[c4 * 4 + 1] = o.y * inv + sB[c4 * 4 + 1];
        h2[c4 * 4 + 2] = o.z * inv + sB[c4 * 4 + 2];
        h2[c4 * 4 + 3] = o.w * inv + sB[c4 * 4 + 3];
    }

    ull acc[32];
    // ---- EA = h2 @ Wa + b1 (fp16 store) ----
#pragma unroll
    for (int i = 0; i < 32; i++) acc[i] = 0ULL;
#pragma unroll 4
    for (int k = 0; k < 64; k++) {
        ull hv = pack2(h2[k]);
        const ulonglong2* wr = (const ulonglong2*)&sWa[k * 64];
#pragma unroll
        for (int c8 = 0; c8 < 16; c8++) {
            ulonglong2 w = wr[c8];
            fma2(acc[2 * c8], hv, w.x);
            fma2(acc[2 * c8 + 1], hv, w.y);
        }
    }
#pragma unroll
    for (int q = 0; q < 8; q++) {
        float2 f0 = unpack2(acc[q * 4]),     f1 = unpack2(acc[q * 4 + 1]);
        float2 f2 = unpack2(acc[q * 4 + 2]), f3 = unpack2(acc[q * 4 + 3]);
        int c = q * 8;
        uint4 u = make_uint4(h2bits(f0.x + sB1[c], f0.y + sB1[c + 1]),
                             h2bits(f1.x + sB1[c + 2], f1.y + sB1[c + 3]),
                             h2bits(f2.x + sB1[c + 4], f2.y + sB1[c + 5]),
                             h2bits(f3.x + sB1[c + 6], f3.y + sB1[c + 7]));
        *(uint4*)&g_EAv[node * 16 + q * 2] = u;
    }
    // ---- EB = h2 @ Wb (fp32) ----
#pragma unroll
    for (int i = 0; i < 32; i++) acc[i] = 0ULL;
#pragma unroll 4
    for (int k = 0; k < 64; k++) {
        ull hv = pack2(h2[k]);
        const ulonglong2* wr = (const ulonglong2*)&sWb[k * 64];
#pragma unroll
        for (int c8 = 0; c8 < 16; c8++) {
            ulonglong2 w = wr[c8];
            fma2(acc[2 * c8], hv, w.x);
            fma2(acc[2 * c8 + 1], hv, w.y);
        }
    }
#pragma unroll
    for (int q = 0; q < 16; q++) {
        float2 f0 = unpack2(acc[q * 2]), f1 = unpack2(acc[q * 2 + 1]);
        *(float4*)&g_EB[node * 64 + q * 4] = make_float4(f0.x, f0.y, f1.x, f1.y);
    }
    // ---- node head ----
#pragma unroll
    for (int i = 0; i < 32; i++) acc[i] = 0ULL;
#pragma unroll 4
    for (int k = 0; k < 64; k++) {
        ull hv = pack2(h2[k]);
        const ulonglong2* wr = (const ulonglong2*)&sWn[k * 64];
#pragma unroll
        for (int c8 = 0; c8 < 16; c8++) {
            ulonglong2 w = wr[c8];
            fma2(acc[2 * c8], hv, w.x);
            fma2(acc[2 * c8 + 1], hv, w.y);
        }
    }
    float p0 = 0.f, p1 = 0.f;
#pragma unroll
    for (int i = 0; i < 32; i++) {
        float2 f = unpack2(acc[i]);
        float t0 = lrelu(f.x + sBn[2 * i], 0.01f);
        float t1 = lrelu(f.y + sBn[2 * i + 1], 0.01f);
        p0 = fmaf(t0, sW2[4 * i],     fmaf(t1, sW2[4 * i + 2], p0));
        p1 = fmaf(t0, sW2[4 * i + 1], fmaf(t1, sW2[4 * i + 3], p1));
    }
    out[e + node * 2]     = tanha(p0 + nob2[0]);
    out[e + node * 2 + 1] = tanha(p1 + nob2[1]);
}

// ==================== kernel: edge head (16 lanes/node, 2 nodes/warp) ========
__global__ void k_edgehead(const float* __restrict__ eattr,
                           const float* __restrict__ eoW1,
                           const float* __restrict__ eoW2, const float* __restrict__ eob2,
                           float* __restrict__ out, int n) {
    int grp = (blockIdx.x * blockDim.x + threadIdx.x) >> 4;
    if (grp >= n) return;
    int node = grp;
    int lh = threadIdx.x & 15;
    unsigned gbase = threadIdx.x & 16;
    unsigned mask = 0xFFFFu << gbase;
    int beg = g_offs[node], end = g_offs[node + 1];
    if (beg == end) return;

    float4 w128 = *(const float4*)&eoW1[128 * 64 + lh * 4];
    float4 w129 = *(const float4*)&eoW1[129 * 64 + lh * 4];
    float4 w2   = *(const float4*)&eoW2[lh * 4];
    float  b2   = eob2[0];
    float4 eb   = *(const float4*)&g_EB[node * 64 + lh * 4];  // dst part, loaded once

    for (int i = beg; i < end; i += 4) {
        int idx = i + (lh >> 2);
        int2 ce = (idx < end) ? g_csr[idx] : make_int2(0, 0);
        float2 ea = *(const float2*)&eattr[ce.y * 2];
#pragma unroll
        for (int k = 0; k < 4; k++) {
            if (i + k >= end) break;
            int   src = __shfl_sync(mask, ce.x, gbase + k * 4);
            float ex  = __shfl_sync(mask, ea.x, gbase + k * 4);
            float ey  = __shfl_sync(mask, ea.y, gbase + k * 4);
            uint2 vb = g_EAv[src * 16 + lh];
            float2 va0 = h2f2(vb.x), va1 = h2f2(vb.y);
            float pre0 = va0.x + eb.x + ex * w128.x + ey * w129.x;
            float pre1 = va0.y + eb.y + ex * w128.y + ey * w129.y;
            float pre2 = va1.x + eb.z + ex * w128.z + ey * w129.z;
            float pre3 = va1.y + eb.w + ex * w128.w + ey * w129.w;
            float p = lrelu(pre0, 0.01f) * w2.x + lrelu(pre1, 0.01f) * w2.y
                    + lrelu(pre2, 0.01f) * w2.z + lrelu(pre3, 0.01f) * w2.w;
            p += __shfl_xor_sync(mask, p, 8);
            p += __shfl_xor_sync(mask, p, 4);
            p += __shfl_xor_sync(mask, p, 2);
            p += __shfl_xor_sync(mask, p, 1);
            int eid = __shfl_sync(mask, ce.y, gbase + k * 4);
            if (lh == 0) out[eid] = tanha(p + b2);
        }
    }
}

// ==================== launch ==================================================
extern "C" void kernel_launch(void* const* d_in, const int* in_sizes, int n_in,
                              void* d_out, int out_size) {
    const float* x      = (const float*)d_in[0];
    const int*   eidx   = (const int*)d_in[1];
    const float* eattr  = (const float*)d_in[2];
    const float* encW   = (const float*)d_in[3];
    const float* encb   = (const float*)d_in[4];
    const float* g1W    = (const float*)d_in[5];
    const float* g1as   = (const float*)d_in[6];
    const float* g1ad   = (const float*)d_in[7];
    const float* g1b    = (const float*)d_in[8];
    const float* g2W    = (const float*)d_in[9];
    const float* g2as   = (const float*)d_in[10];
    const float* g2ad   = (const float*)d_in[11];
    const float* g2b    = (const float*)d_in[12];
    const float* noW1   = (const float*)d_in[13];
    const float* nob1   = (const float*)d_in[14];
    const float* noW2   = (const float*)d_in[15];
    const float* nob2   = (const float*)d_in[16];
    const float* eoW1   = (const float*)d_in[17];
    const float* eob1   = (const float*)d_in[18];
    const float* eoW2   = (const float*)d_in[19];
    const float* eob2   = (const float*)d_in[20];
    float* out = (float*)d_out;

    int n = in_sizes[0] / 2;
    int e = in_sizes[1] / 2;
    const int* src = eidx;
    const int* dst = eidx + e;

    const int B = 256;
    int gn   = (n + B - 1) / B;
    int ge   = (e + B - 1) / B;
    int gw16 = (n * 16 + B - 1) / B;   // 16 lanes per node

    // CSR build (dst-sorted) — g_cnt is zero on entry (static init / re-zeroed below)
    k_hist<<<ge, B>>>(dst, e);
    k_sumscan<<<1, 1024>>>(n);
    k_scanwrite<<<NCHUNK, 1024>>>(n);
    k_scatter<<<ge, B>>>(src, dst, e);

    // pipeline
    k_pre<<<1, 64>>>(encW, encb, g1W);
    k_enc_gat1<<<gn, B>>>(x, g1as, g1ad, n);
    k_msg1<<<gw16, B>>>(n);
    k_fin1_gat2<<<gn, B>>>(g1b, g2W, g2as, g2ad, n);
    k_msg2<<<gw16, B>>>(n);
    k_fin2_heads<<<gn, B>>>(g2b, eoW1, eob1, noW1, nob1, noW2, nob2, out, n, e);
    k_edgehead<<<gw16, B>>>(eattr, eoW1, eoW2, eob2, out, n);
}

// round 8
// speedup vs baseline: 1.0704x; 1.0704x over previous
#include <cuda_runtime.h>
#include <cuda_fp16.h>

#define NN 100000
#define EE 1600000
#define NCHUNK 128
#define CH 782   // ceil(100000/128)

// ---------------- scratch (static device globals) ----------------------------
__device__ unsigned int g_hp1h[NN * 32];   // half2 bit patterns, 64ch/node
__device__ float g_out1[NN * 64];
__device__ float g_as1[NN * 4];
__device__ float g_ad1[NN * 4];
__device__ float g_asum1[NN * 4];
__device__ unsigned int g_hp2h[NN * 32];
__device__ float g_out2[NN * 64];
__device__ float g_as2[NN];
__device__ float g_ad2[NN];
__device__ float g_asum2[NN];
__device__ unsigned int g_EAh[NN * 32];    // fp16 EA
__device__ float g_EB[NN * 64];
// rank-2 encoder precompute
__device__ float g_P0[64], g_P1[64], g_Pb[64];
// CSR build
__device__ int  g_cnt[NN];                 // zero on entry; re-zeroed in k_scanwrite
__device__ int  g_offs[NN + 1];
__device__ int  g_cur[NN];
__device__ int2 g_csr[EE];                 // .x = src node, .y = edge id
__device__ int  g_boff[NCHUNK];

// ---------------- helpers ----------------------------------------------------
__device__ __forceinline__ float lrelu(float x, float s) { return x > 0.f ? x : s * x; }
__device__ __forceinline__ float tanha(float x) {
    float r; asm("tanh.approx.f32 %0, %1;" : "=f"(r) : "f"(x)); return r;
}

typedef unsigned long long ull;
__device__ __forceinline__ ull pack2(float v) {
    ull r;
    unsigned int u = __float_as_uint(v);
    asm("mov.b64 %0, {%1, %1};" : "=l"(r) : "r"(u));
    return r;
}
__device__ __forceinline__ void fma2(ull& d, ull a, ull b) {
    asm("fma.rn.f32x2 %0, %1, %2, %3;" : "=l"(d) : "l"(a), "l"(b), "l"(d));
}
__device__ __forceinline__ float2 unpack2(ull v) {
    unsigned int lo, hi;
    asm("mov.b64 {%0, %1}, %2;" : "=r"(lo), "=r"(hi) : "l"(v));
    return make_float2(__uint_as_float(lo), __uint_as_float(hi));
}
__device__ __forceinline__ unsigned int h2bits(float a, float b) {
    __half2 h = __floats2half2_rn(a, b);
    return *(unsigned int*)&h;
}
__device__ __forceinline__ float2 h2f2(unsigned int b) {
    return __half22float2(*(__half2*)&b);
}

// ==================== CSR build ==============================================
__global__ void k_hist(const int* __restrict__ dst, int e) {
    int t = blockIdx.x * blockDim.x + threadIdx.x;
    if (t < e) atomicAdd(&g_cnt[dst[t]], 1);
}
// one block: per-chunk totals (8 threads/chunk) + scan over 128 chunks
__global__ void k_sumscan(int n) {
    __shared__ int ssum[NCHUNK];
    int t = threadIdx.x;                   // 1024
    int chunk = t >> 3, sub = t & 7;
    int base = chunk * CH;
    int s = 0;
    for (int i = sub; i < CH; i += 8) {
        int idx = base + i;
        if (idx < n) s += g_cnt[idx];
    }
    s += __shfl_xor_sync(0xffffffffu, s, 1);
    s += __shfl_xor_sync(0xffffffffu, s, 2);
    s += __shfl_xor_sync(0xffffffffu, s, 4);
    if (sub == 0) ssum[chunk] = s;
    __syncthreads();
    int tot = (t < NCHUNK) ? ssum[t] : 0;
    for (int o = 1; o < NCHUNK; o <<= 1) {
        int x = (t < NCHUNK && t >= o) ? ssum[t - o] : 0;
        __syncthreads();
        if (t < NCHUNK) ssum[t] += x;
        __syncthreads();
    }
    if (t < NCHUNK) g_boff[t] = ssum[t] - tot;   // exclusive
}
__global__ void k_scanwrite(int n) {
    __shared__ int sd[1024];
    int b = blockIdx.x, t = threadIdx.x;
    int base = b * CH;
    int v = (t < CH && base + t < n) ? g_cnt[base + t] : 0;
    sd[t] = v; __syncthreads();
    for (int o = 1; o < 1024; o <<= 1) {
        int x = (t >= o) ? sd[t - o] : 0;
        __syncthreads();
        sd[t] += x;
        __syncthreads();
    }
    int excl = sd[t] - v + g_boff[b];
    if (t < CH && base + t < n) {
        g_offs[base + t] = excl;
        g_cur[base + t] = excl;
        g_cnt[base + t] = 0;               // re-zero for next graph replay
    }
    if (base + t == n - 1) g_offs[n] = excl + v;
}
__global__ void k_scatter(const int* __restrict__ src, const int* __restrict__ dst, int e) {
    int t = blockIdx.x * blockDim.x + threadIdx.x;
    if (t >= e) return;
    int d = dst[t];
    int pos = atomicAdd(&g_cur[d], 1);
    g_csr[pos] = make_int2(src[t], t);
}

// ==================== kernel: rank-2 encoder precompute ======================
__global__ void k_pre(const float* __restrict__ encW, const float* __restrict__ encb,
                      const float* __restrict__ g1W) {
    int c = threadIdx.x;           // 64 threads
    float p0 = 0.f, p1 = 0.f, pb = 0.f;
    for (int k = 0; k < 64; k++) {
        float w = g1W[k * 64 + c];
        p0 = fmaf(encW[k], w, p0);
        p1 = fmaf(encW[64 + k], w, p1);
        pb = fmaf(encb[k], w, pb);
    }
    g_P0[c] = p0; g_P1[c] = p1; g_Pb[c] = pb;
}

// ==================== kernel: encoder+gat1 projection (rank-2) ===============
__global__ void k_enc_gat1(const float* __restrict__ x,
                           const float* __restrict__ g1as, const float* __restrict__ g1ad,
                           int n) {
    __shared__ __align__(16) float sP0[64], sP1[64], sPb[64], sAs[64], sAd[64];
    if (threadIdx.x < 64) {
        sP0[threadIdx.x] = g_P0[threadIdx.x];
        sP1[threadIdx.x] = g_P1[threadIdx.x];
        sPb[threadIdx.x] = g_Pb[threadIdx.x];
        sAs[threadIdx.x] = g1as[threadIdx.x];
        sAd[threadIdx.x] = g1ad[threadIdx.x];
    }
    __syncthreads();
    int node = blockIdx.x * blockDim.x + threadIdx.x;
    if (node >= n) return;

    float2 xv = *(const float2*)&x[node * 2];
    float hp[64];
    float asv[4] = {0, 0, 0, 0}, adv[4] = {0, 0, 0, 0};
#pragma unroll
    for (int c = 0; c < 64; c++) {
        float v = fmaf(xv.x, sP0[c], fmaf(xv.y, sP1[c], sPb[c]));
        hp[c] = v;
        asv[c >> 4] = fmaf(v, sAs[c], asv[c >> 4]);
        adv[c >> 4] = fmaf(v, sAd[c], adv[c >> 4]);
    }
    float es[4];
#pragma unroll
    for (int h = 0; h < 4; h++) {
        g_as1[node * 4 + h] = asv[h];
        g_ad1[node * 4 + h] = adv[h];
        es[h] = __expf(lrelu(asv[h] + adv[h], 0.2f));
    }
    *(float4*)&g_asum1[node * 4] = make_float4(es[0], es[1], es[2], es[3]);
#pragma unroll
    for (int q = 0; q < 8; q++) {
        int c = q * 8;
        uint4 u = make_uint4(h2bits(hp[c], hp[c + 1]), h2bits(hp[c + 2], hp[c + 3]),
                             h2bits(hp[c + 4], hp[c + 5]), h2bits(hp[c + 6], hp[c + 7]));
        *(uint4*)&g_hp1h[node * 32 + q * 4] = u;
        float e0 = es[c >> 4];
        *(float4*)&g_out1[node * 64 + c] =
            make_float4(hp[c] * e0, hp[c + 1] * e0, hp[c + 2] * e0, hp[c + 3] * e0);
        *(float4*)&g_out1[node * 64 + c + 4] =
            make_float4(hp[c + 4] * e0, hp[c + 5] * e0, hp[c + 6] * e0, hp[c + 7] * e0);
    }
}

// ==================== kernel: gat1 gather (warp/node, batched MLP=8) =========
__global__ void k_msg1(int n) {
    int warp = (blockIdx.x * blockDim.x + threadIdx.x) >> 5;
    if (warp >= n) return;
    int node = warp;
    int lane = threadIdx.x & 31;
    int beg = g_offs[node], end = g_offs[node + 1];

    float adh = g_ad1[node * 4 + (lane & 3)];
    float2 acc = *(const float2*)&g_out1[node * 64 + lane * 2];
    float wsum = 0.f;

    int i = beg;
    // full strips: no bounds predicates anywhere
    for (; i + 8 <= end; i += 8) {
        int idx = i + (lane >> 2);                // 8 edges, 4 lanes each
        int2 ce = g_csr[idx];
        float a = g_as1[ce.x * 4 + (lane & 3)] + adh;
        float w8 = __expf(lrelu(a, 0.2f));
        wsum += w8;
        int ss[8];
#pragma unroll
        for (int k = 0; k < 8; k++) ss[k] = __shfl_sync(0xffffffffu, ce.x, k * 4);
        float2 vv[8];
#pragma unroll
        for (int k = 0; k < 8; k++) vv[k] = h2f2(g_hp1h[ss[k] * 32 + lane]);
#pragma unroll
        for (int k = 0; k < 8; k++) {
            float wl = __shfl_sync(0xffffffffu, w8, k * 4 + (lane >> 3));
            acc.x = fmaf(wl, vv[k].x, acc.x);
            acc.y = fmaf(wl, vv[k].y, acc.y);
        }
    }
    // padded tail strip
    if (i < end) {
        int idx = i + (lane >> 2);
        int2 ce = (idx < end) ? g_csr[idx] : make_int2(node, 0);
        float a = g_as1[ce.x * 4 + (lane & 3)] + adh;
        float w8 = (idx < end) ? __expf(lrelu(a, 0.2f)) : 0.f;
        wsum += w8;
        int ss[8];
#pragma unroll
        for (int k = 0; k < 8; k++) ss[k] = __shfl_sync(0xffffffffu, ce.x, k * 4);
        float2 vv[8];
#pragma unroll
        for (int k = 0; k < 8; k++) vv[k] = h2f2(g_hp1h[ss[k] * 32 + lane]);
#pragma unroll
        for (int k = 0; k < 8; k++) {
            float wl = __shfl_sync(0xffffffffu, w8, k * 4 + (lane >> 3));
            acc.x = fmaf(wl, vv[k].x, acc.x);
            acc.y = fmaf(wl, vv[k].y, acc.y);
        }
    }
    *(float2*)&g_out1[node * 64 + lane * 2] = acc;
    wsum += __shfl_xor_sync(0xffffffffu, wsum, 4);
    wsum += __shfl_xor_sync(0xffffffffu, wsum, 8);
    wsum += __shfl_xor_sync(0xffffffffu, wsum, 16);
    if (lane < 4) g_asum1[node * 4 + lane] += wsum;
}

// ==================== kernel: finish gat1 + gat2 projection (FFMA2) ==========
__global__ void k_fin1_gat2(const float* __restrict__ g1b,
                            const float* __restrict__ g2W,
                            const float* __restrict__ g2as, const float* __restrict__ g2ad,
                            int n) {
    __shared__ __align__(16) float sW[64 * 64];
    __shared__ __align__(16) float sB[64], sAs[64], sAd[64];
    for (int i = threadIdx.x; i < 4096; i += blockDim.x) sW[i] = g2W[i];
    if (threadIdx.x < 64) {
        sB[threadIdx.x] = g1b[threadIdx.x];
        sAs[threadIdx.x] = g2as[threadIdx.x];
        sAd[threadIdx.x] = g2ad[threadIdx.x];
    }
    __syncthreads();
    int node = blockIdx.x * blockDim.x + threadIdx.x;
    if (node >= n) return;

    float inv[4];
#pragma unroll
    for (int h = 0; h < 4; h++) inv[h] = 1.0f / g_asum1[node * 4 + h];

    ull acc[32];
#pragma unroll
    for (int i = 0; i < 32; i++) acc[i] = 0ULL;
#pragma unroll 2
    for (int k4 = 0; k4 < 16; k4++) {
        float4 o = *(const float4*)&g_out1[node * 64 + k4 * 4];
        float iv = inv[k4 >> 2];
        float hv4[4];
        hv4[0] = o.x * iv + sB[k4 * 4];
        hv4[1] = o.y * iv + sB[k4 * 4 + 1];
        hv4[2] = o.z * iv + sB[k4 * 4 + 2];
        hv4[3] = o.w * iv + sB[k4 * 4 + 3];
#pragma unroll
        for (int j = 0; j < 4; j++) {
            float hj = hv4[j] > 0.f ? hv4[j] : expm1f(hv4[j]);
            ull hv = pack2(hj);
            const ulonglong2* wr = (const ulonglong2*)&sW[(k4 * 4 + j) * 64];
#pragma unroll
            for (int c8 = 0; c8 < 16; c8++) {
                ulonglong2 w = wr[c8];
                fma2(acc[2 * c8], hv, w.x);
                fma2(acc[2 * c8 + 1], hv, w.y);
            }
        }
    }
    float hp[64];
#pragma unroll
    for (int i = 0; i < 32; i++) {
        float2 f = unpack2(acc[i]);
        hp[2 * i] = f.x; hp[2 * i + 1] = f.y;
    }
    float as = 0.f, ad = 0.f;
#pragma unroll
    for (int c = 0; c < 64; c++) {
        as = fmaf(hp[c], sAs[c], as);
        ad = fmaf(hp[c], sAd[c], ad);
    }
    g_as2[node] = as;
    g_ad2[node] = ad;
    float es = __expf(lrelu(as + ad, 0.2f));
    g_asum2[node] = es;
#pragma unroll
    for (int q = 0; q < 8; q++) {
        int c = q * 8;
        uint4 u = make_uint4(h2bits(hp[c], hp[c + 1]), h2bits(hp[c + 2], hp[c + 3]),
                             h2bits(hp[c + 4], hp[c + 5]), h2bits(hp[c + 6], hp[c + 7]));
        *(uint4*)&g_hp2h[node * 32 + q * 4] = u;
        *(float4*)&g_out2[node * 64 + c] =
            make_float4(hp[c] * es, hp[c + 1] * es, hp[c + 2] * es, hp[c + 3] * es);
        *(float4*)&g_out2[node * 64 + c + 4] =
            make_float4(hp[c + 4] * es, hp[c + 5] * es, hp[c + 6] * es, hp[c + 7] * es);
    }
}

// ==================== kernel: gat2 gather (warp/node, batched MLP=8) =========
__global__ void k_msg2(int n) {
    int warp = (blockIdx.x * blockDim.x + threadIdx.x) >> 5;
    if (warp >= n) return;
    int node = warp;
    int lane = threadIdx.x & 31;
    int beg = g_offs[node], end = g_offs[node + 1];

    float ad2 = g_ad2[node];
    float2 acc = *(const float2*)&g_out2[node * 64 + lane * 2];
    float wsum = 0.f;

    for (int i = beg; i < end; i += 32) {
        int idx = i + lane;
        int2 ce = (idx < end) ? g_csr[idx] : make_int2(0, 0);
        float a = g_as2[ce.x] + ad2;
        float w32 = (idx < end) ? __expf(lrelu(a, 0.2f)) : 0.f;
        wsum += w32;
#pragma unroll
        for (int kk = 0; kk < 4; kk++) {
            if (i + kk * 8 >= end) break;
            int ss[8];
#pragma unroll
            for (int k = 0; k < 8; k++) ss[k] = __shfl_sync(0xffffffffu, ce.x, kk * 8 + k);
            float2 vv[8];
#pragma unroll
            for (int k = 0; k < 8; k++) vv[k] = h2f2(g_hp2h[ss[k] * 32 + lane]);
#pragma unroll
            for (int k = 0; k < 8; k++) {
                float wl = __shfl_sync(0xffffffffu, w32, kk * 8 + k);
                acc.x = fmaf(wl, vv[k].x, acc.x);
                acc.y = fmaf(wl, vv[k].y, acc.y);
            }
        }
    }
    *(float2*)&g_out2[node * 64 + lane * 2] = acc;
    wsum += __shfl_xor_sync(0xffffffffu, wsum, 16);
    wsum += __shfl_xor_sync(0xffffffffu, wsum, 8);
    wsum += __shfl_xor_sync(0xffffffffu, wsum, 4);
    wsum += __shfl_xor_sync(0xffffffffu, wsum, 2);
    wsum += __shfl_xor_sync(0xffffffffu, wsum, 1);
    if (lane == 0) g_asum2[node] += wsum;
}

// ==================== kernel: finish gat2 + EA/EB + node head (FFMA2) ========
__global__ void k_fin2_heads(const float* __restrict__ g2b,
                             const float* __restrict__ eoW1, const float* __restrict__ eob1,
                             const float* __restrict__ noW1, const float* __restrict__ nob1,
                             const float* __restrict__ noW2, const float* __restrict__ nob2,
                             float* __restrict__ out, int n, int e) {
    __shared__ __align__(16) float sWa[64 * 64];
    __shared__ __align__(16) float sWb[64 * 64];
    __shared__ __align__(16) float sWn[64 * 64];
    __shared__ __align__(16) float sB[64], sB1[64], sBn[64], sW2[128];
    for (int i = threadIdx.x; i < 4096; i += blockDim.x) {
        sWa[i] = eoW1[i];
        sWb[i] = eoW1[4096 + i];
        sWn[i] = noW1[i];
    }
    if (threadIdx.x < 64) {
        sB[threadIdx.x]  = g2b[threadIdx.x];
        sB1[threadIdx.x] = eob1[threadIdx.x];
        sBn[threadIdx.x] = nob1[threadIdx.x];
    }
    if (threadIdx.x < 128) sW2[threadIdx.x] = noW2[threadIdx.x];
    __syncthreads();
    int node = blockIdx.x * blockDim.x + threadIdx.x;
    if (node >= n) return;

    float inv = 1.0f / g_asum2[node];
    float h2[64];
#pragma unroll
    for (int c4 = 0; c4 < 16; c4++) {
        float4 o = *(const float4*)&g_out2[node * 64 + c4 * 4];
        h2[c4 * 4]     = o.x * inv + sB[c4 * 4];
        h2[c4 * 4 + 1] = o.y * inv + sB[c4 * 4 + 1];
        h2[c4 * 4 + 2] = o.z * inv + sB[c4 * 4 + 2];
        h2[c4 * 4 + 3] = o.w * inv + sB[c4 * 4 + 3];
    }

    ull acc[32];
    // ---- EA = h2 @ Wa + b1 (fp16 store) ----
#pragma unroll
    for (int i = 0; i < 32; i++) acc[i] = 0ULL;
#pragma unroll 4
    for (int k = 0; k < 64; k++) {
        ull hv = pack2(h2[k]);
        const ulonglong2* wr = (const ulonglong2*)&sWa[k * 64];
#pragma unroll
        for (int c8 = 0; c8 < 16; c8++) {
            ulonglong2 w = wr[c8];
            fma2(acc[2 * c8], hv, w.x);
            fma2(acc[2 * c8 + 1], hv, w.y);
        }
    }
#pragma unroll
    for (int q = 0; q < 8; q++) {
        float2 f0 = unpack2(acc[q * 4]),     f1 = unpack2(acc[q * 4 + 1]);
        float2 f2 = unpack2(acc[q * 4 + 2]), f3 = unpack2(acc[q * 4 + 3]);
        int c = q * 8;
        uint4 u = make_uint4(h2bits(f0.x + sB1[c], f0.y + sB1[c + 1]),
                             h2bits(f1.x + sB1[c + 2], f1.y + sB1[c + 3]),
                             h2bits(f2.x + sB1[c + 4], f2.y + sB1[c + 5]),
                             h2bits(f3.x + sB1[c + 6], f3.y + sB1[c + 7]));
        *(uint4*)&g_EAh[node * 32 + q * 4] = u;
    }
    // ---- EB = h2 @ Wb (fp32) ----
#pragma unroll
    for (int i = 0; i < 32; i++) acc[i] = 0ULL;
#pragma unroll 4
    for (int k = 0; k < 64; k++) {
        ull hv = pack2(h2[k]);
        const ulonglong2* wr = (const ulonglong2*)&sWb[k * 64];
#pragma unroll
        for (int c8 = 0; c8 < 16; c8++) {
            ulonglong2 w = wr[c8];
            fma2(acc[2 * c8], hv, w.x);
            fma2(acc[2 * c8 + 1], hv, w.y);
        }
    }
#pragma unroll
    for (int q = 0; q < 16; q++) {
        float2 f0 = unpack2(acc[q * 2]), f1 = unpack2(acc[q * 2 + 1]);
        *(float4*)&g_EB[node * 64 + q * 4] = make_float4(f0.x, f0.y, f1.x, f1.y);
    }
    // ---- node head ----
#pragma unroll
    for (int i = 0; i < 32; i++) acc[i] = 0ULL;
#pragma unroll 4
    for (int k = 0; k < 64; k++) {
        ull hv = pack2(h2[k]);
        const ulonglong2* wr = (const ulonglong2*)&sWn[k * 64];
#pragma unroll
        for (int c8 = 0; c8 < 16; c8++) {
            ulonglong2 w = wr[c8];
            fma2(acc[2 * c8], hv, w.x);
            fma2(acc[2 * c8 + 1], hv, w.y);
        }
    }
    float p0 = 0.f, p1 = 0.f;
#pragma unroll
    for (int i = 0; i < 32; i++) {
        float2 f = unpack2(acc[i]);
        float t0 = lrelu(f.x + sBn[2 * i], 0.01f);
        float t1 = lrelu(f.y + sBn[2 * i + 1], 0.01f);
        p0 = fmaf(t0, sW2[4 * i],     fmaf(t1, sW2[4 * i + 2], p0));
        p1 = fmaf(t0, sW2[4 * i + 1], fmaf(t1, sW2[4 * i + 3], p1));
    }
    out[e + node * 2]     = tanha(p0 + nob2[0]);
    out[e + node * 2 + 1] = tanha(p1 + nob2[1]);
}

// ==================== kernel: edge head (warp/node, batched MLP=8) ===========
__global__ void k_edgehead(const float* __restrict__ eattr,
                           const float* __restrict__ eoW1,
                           const float* __restrict__ eoW2, const float* __restrict__ eob2,
                           float* __restrict__ out, int n) {
    int warp = (blockIdx.x * blockDim.x + threadIdx.x) >> 5;
    if (warp >= n) return;
    int node = warp;
    int lane = threadIdx.x & 31;
    int beg = g_offs[node], end = g_offs[node + 1];
    if (beg == end) return;

    float2 w128 = *(const float2*)&eoW1[128 * 64 + lane * 2];
    float2 w129 = *(const float2*)&eoW1[129 * 64 + lane * 2];
    float2 w2   = *(const float2*)&eoW2[lane * 2];
    float  b2   = eob2[0];
    float2 eb   = *(const float2*)&g_EB[node * 64 + lane * 2];

    for (int i = beg; i < end; i += 32) {
        int idx = i + lane;
        int2 ce = (idx < end) ? g_csr[idx] : make_int2(0, 0);
        float2 ea = *(const float2*)&eattr[ce.y * 2];
#pragma unroll
        for (int kk = 0; kk < 4; kk++) {
            if (i + kk * 8 >= end) break;
            int ss[8], ei[8];
            float ex[8], ey[8];
#pragma unroll
            for (int k = 0; k < 8; k++) {
                ss[k] = __shfl_sync(0xffffffffu, ce.x, kk * 8 + k);
                ei[k] = __shfl_sync(0xffffffffu, ce.y, kk * 8 + k);
                ex[k] = __shfl_sync(0xffffffffu, ea.x, kk * 8 + k);
                ey[k] = __shfl_sync(0xffffffffu, ea.y, kk * 8 + k);
            }
            float2 va[8];
#pragma unroll
            for (int k = 0; k < 8; k++) va[k] = h2f2(g_EAh[ss[k] * 32 + lane]);
            float p[8];
#pragma unroll
            for (int k = 0; k < 8; k++) {
                float pre0 = va[k].x + eb.x + ex[k] * w128.x + ey[k] * w129.x;
                float pre1 = va[k].y + eb.y + ex[k] * w128.y + ey[k] * w129.y;
                p[k] = lrelu(pre0, 0.01f) * w2.x + lrelu(pre1, 0.01f) * w2.y;
            }
#pragma unroll
            for (int k = 0; k < 8; k++) {
                p[k] += __shfl_xor_sync(0xffffffffu, p[k], 16);
                p[k] += __shfl_xor_sync(0xffffffffu, p[k], 8);
                p[k] += __shfl_xor_sync(0xffffffffu, p[k], 4);
                p[k] += __shfl_xor_sync(0xffffffffu, p[k], 2);
                p[k] += __shfl_xor_sync(0xffffffffu, p[k], 1);
            }
#pragma unroll
            for (int k = 0; k < 8; k++)
                if (lane == 0 && (i + kk * 8 + k) < end) out[ei[k]] = tanha(p[k] + b2);
        }
    }
}

// ==================== launch ==================================================
extern "C" void kernel_launch(void* const* d_in, const int* in_sizes, int n_in,
                              void* d_out, int out_size) {
    const float* x      = (const float*)d_in[0];
    const int*   eidx   = (const int*)d_in[1];
    const float* eattr  = (const float*)d_in[2];
    const float* encW   = (const float*)d_in[3];
    const float* encb   = (const float*)d_in[4];
    const float* g1W    = (const float*)d_in[5];
    const float* g1as   = (const float*)d_in[6];
    const float* g1ad   = (const float*)d_in[7];
    const float* g1b    = (const float*)d_in[8];
    const float* g2W    = (const float*)d_in[9];
    const float* g2as   = (const float*)d_in[10];
    const float* g2ad   = (const float*)d_in[11];
    const float* g2b    = (const float*)d_in[12];
    const float* noW1   = (const float*)d_in[13];
    const float* nob1   = (const float*)d_in[14];
    const float* noW2   = (const float*)d_in[15];
    const float* nob2   = (const float*)d_in[16];
    const float* eoW1   = (const float*)d_in[17];
    const float* eob1   = (const float*)d_in[18];
    const float* eoW2   = (const float*)d_in[19];
    const float* eob2   = (const float*)d_in[20];
    float* out = (float*)d_out;

    int n = in_sizes[0] / 2;
    int e = in_sizes[1] / 2;
    const int* src = eidx;
    const int* dst = eidx + e;

    const int B = 256;
    int gn = (n + B - 1) / B;
    int ge = (e + B - 1) / B;
    int gw = (n * 32 + B - 1) / B;

    // CSR build (dst-sorted) — g_cnt zero on entry, re-zeroed inside k_scanwrite
    k_hist<<<ge, B>>>(dst, e);
    k_sumscan<<<1, 1024>>>(n);
    k_scanwrite<<<NCHUNK, 1024>>>(n);
    k_scatter<<<ge, B>>>(src, dst, e);

    // pipeline
    k_pre<<<1, 64>>>(encW, encb, g1W);
    k_enc_gat1<<<gn, B>>>(x, g1as, g1ad, n);
    k_msg1<<<gw, B>>>(n);
    k_fin1_gat2<<<gn, B>>>(g1b, g2W, g2as, g2ad, n);
    k_msg2<<<gw, B>>>(n);
    k_fin2_heads<<<gn, B>>>(g2b, eoW1, eob1, noW1, nob1, noW2, nob2, out, n, e);
    k_edgehead<<<gw, B>>>(eattr, eoW1, eoW2, eob2, out, n);
}

// round 9
// speedup vs baseline: 1.0996x; 1.0273x over previous
#include <cuda_runtime.h>
#include <cuda_fp16.h>

#define NN 100000
#define EE 1600000
#define NCHUNK 128
#define CH 782   // ceil(100000/128)

// ---------------- scratch (static device globals) ----------------------------
__device__ unsigned int g_hp1h[NN * 32];   // half2 bit patterns, 64ch/node
__device__ float g_out1[NN * 64];
__device__ float g_as1[NN * 4];
__device__ float g_ad1[NN * 4];
__device__ float g_asum1[NN * 4];
__device__ unsigned int g_hp2h[NN * 32];
__device__ float g_out2[NN * 64];
__device__ float g_as2[NN];
__device__ float g_ad2[NN];
__device__ float g_asum2[NN];
__device__ unsigned int g_EAh[NN * 32];    // fp16 EA
__device__ float g_EB[NN * 64];
// CSR build
__device__ int  g_cnt[NN];                 // zero on entry; re-zeroed in k_scanwrite
__device__ int  g_offs[NN + 1];
__device__ int  g_cur[NN];
__device__ int2 g_csr[EE];                 // .x = src node, .y = edge id
__device__ int  g_boff[NCHUNK];

// ---------------- helpers ----------------------------------------------------
__device__ __forceinline__ float lrelu(float x, float s) { return x > 0.f ? x : s * x; }
__device__ __forceinline__ float tanha(float x) {
    float r; asm("tanh.approx.f32 %0, %1;" : "=f"(r) : "f"(x)); return r;
}

typedef unsigned long long ull;
__device__ __forceinline__ ull pack2(float v) {
    ull r;
    unsigned int u = __float_as_uint(v);
    asm("mov.b64 %0, {%1, %1};" : "=l"(r) : "r"(u));
    return r;
}
__device__ __forceinline__ void fma2(ull& d, ull a, ull b) {
    asm("fma.rn.f32x2 %0, %1, %2, %3;" : "=l"(d) : "l"(a), "l"(b), "l"(d));
}
__device__ __forceinline__ float2 unpack2(ull v) {
    unsigned int lo, hi;
    asm("mov.b64 {%0, %1}, %2;" : "=r"(lo), "=r"(hi) : "l"(v));
    return make_float2(__uint_as_float(lo), __uint_as_float(hi));
}
__device__ __forceinline__ unsigned int h2bits(float a, float b) {
    __half2 h = __floats2half2_rn(a, b);
    return *(unsigned int*)&h;
}
__device__ __forceinline__ float2 h2f2(unsigned int b) {
    return __half22float2(*(__half2*)&b);
}

// ==================== CSR build ==============================================
__global__ void k_hist(const int* __restrict__ dst, int e) {
    int t = blockIdx.x * blockDim.x + threadIdx.x;
    if (t < e) atomicAdd(&g_cnt[dst[t]], 1);
}
__global__ void k_sumscan(int n) {
    __shared__ int ssum[NCHUNK];
    int t = threadIdx.x;                   // 1024
    int chunk = t >> 3, sub = t & 7;
    int base = chunk * CH;
    int s = 0;
    for (int i = sub; i < CH; i += 8) {
        int idx = base + i;
        if (idx < n) s += g_cnt[idx];
    }
    s += __shfl_xor_sync(0xffffffffu, s, 1);
    s += __shfl_xor_sync(0xffffffffu, s, 2);
    s += __shfl_xor_sync(0xffffffffu, s, 4);
    if (sub == 0) ssum[chunk] = s;
    __syncthreads();
    int tot = (t < NCHUNK) ? ssum[t] : 0;
    for (int o = 1; o < NCHUNK; o <<= 1) {
        int x = (t < NCHUNK && t >= o) ? ssum[t - o] : 0;
        __syncthreads();
        if (t < NCHUNK) ssum[t] += x;
        __syncthreads();
    }
    if (t < NCHUNK) g_boff[t] = ssum[t] - tot;   // exclusive
}
__global__ void k_scanwrite(int n) {
    __shared__ int sd[1024];
    int b = blockIdx.x, t = threadIdx.x;
    int base = b * CH;
    int v = (t < CH && base + t < n) ? g_cnt[base + t] : 0;
    sd[t] = v; __syncthreads();
    for (int o = 1; o < 1024; o <<= 1) {
        int x = (t >= o) ? sd[t - o] : 0;
        __syncthreads();
        sd[t] += x;
        __syncthreads();
    }
    int excl = sd[t] - v + g_boff[b];
    if (t < CH && base + t < n) {
        g_offs[base + t] = excl;
        g_cur[base + t] = excl;
        g_cnt[base + t] = 0;               // re-zero for next graph replay
    }
    if (base + t == n - 1) g_offs[n] = excl + v;
}
__global__ void k_scatter(const int* __restrict__ src, const int* __restrict__ dst, int e) {
    int t = blockIdx.x * blockDim.x + threadIdx.x;
    if (t >= e) return;
    int d = dst[t];
    int pos = atomicAdd(&g_cur[d], 1);
    g_csr[pos] = make_int2(src[t], t);
}

// ==================== kernel: encoder+gat1 projection (rank-2, inline pre) ===
__global__ void k_enc_gat1(const float* __restrict__ x,
                           const float* __restrict__ encW, const float* __restrict__ encb,
                           const float* __restrict__ g1W,
                           const float* __restrict__ g1as, const float* __restrict__ g1ad,
                           int n) {
    __shared__ __align__(16) float sP0[64], sP1[64], sPb[64], sAs[64], sAd[64];
    if (threadIdx.x < 64) {
        int c = threadIdx.x;
        float p0 = 0.f, p1 = 0.f, pb = 0.f;
#pragma unroll 8
        for (int k = 0; k < 64; k++) {
            float w = g1W[k * 64 + c];
            p0 = fmaf(encW[k], w, p0);
            p1 = fmaf(encW[64 + k], w, p1);
            pb = fmaf(encb[k], w, pb);
        }
        sP0[c] = p0; sP1[c] = p1; sPb[c] = pb;
        sAs[c] = g1as[c];
        sAd[c] = g1ad[c];
    }
    __syncthreads();
    int node = blockIdx.x * blockDim.x + threadIdx.x;
    if (node >= n) return;

    float2 xv = *(const float2*)&x[node * 2];
    float hp[64];
    float asv[4] = {0, 0, 0, 0}, adv[4] = {0, 0, 0, 0};
#pragma unroll
    for (int c = 0; c < 64; c++) {
        float v = fmaf(xv.x, sP0[c], fmaf(xv.y, sP1[c], sPb[c]));
        hp[c] = v;
        asv[c >> 4] = fmaf(v, sAs[c], asv[c >> 4]);
        adv[c >> 4] = fmaf(v, sAd[c], adv[c >> 4]);
    }
    float es[4];
#pragma unroll
    for (int h = 0; h < 4; h++) {
        g_as1[node * 4 + h] = asv[h];
        g_ad1[node * 4 + h] = adv[h];
        es[h] = __expf(lrelu(asv[h] + adv[h], 0.2f));
    }
    *(float4*)&g_asum1[node * 4] = make_float4(es[0], es[1], es[2], es[3]);
#pragma unroll
    for (int q = 0; q < 8; q++) {
        int c = q * 8;
        uint4 u = make_uint4(h2bits(hp[c], hp[c + 1]), h2bits(hp[c + 2], hp[c + 3]),
                             h2bits(hp[c + 4], hp[c + 5]), h2bits(hp[c + 6], hp[c + 7]));
        *(uint4*)&g_hp1h[node * 32 + q * 4] = u;
        float e0 = es[c >> 4];
        *(float4*)&g_out1[node * 64 + c] =
            make_float4(hp[c] * e0, hp[c + 1] * e0, hp[c + 2] * e0, hp[c + 3] * e0);
        *(float4*)&g_out1[node * 64 + c + 4] =
            make_float4(hp[c + 4] * e0, hp[c + 5] * e0, hp[c + 6] * e0, hp[c + 7] * e0);
    }
}

// ==================== kernel: gat1 gather (warp/node, pipelined) =============
__global__ void k_msg1(int n) {
    int warp = (blockIdx.x * blockDim.x + threadIdx.x) >> 5;
    if (warp >= n) return;
    int node = warp;
    int lane = threadIdx.x & 31;
    int beg = g_offs[node], end = g_offs[node + 1];

    float adh = g_ad1[node * 4 + (lane & 3)];
    float2 acc = *(const float2*)&g_out1[node * 64 + lane * 2];
    float wsum = 0.f;

    int i = beg;
    // prefetch strip 0 (padded)
    int idx0 = i + (lane >> 2);
    int2 ce = (idx0 < end) ? g_csr[idx0] : make_int2(node, 0);
    float av = g_as1[ce.x * 4 + (lane & 3)];

    // full strips: current strip is complete; prefetch next while processing
    for (; i + 8 <= end; ) {
        int inext = i + 8;
        int2 ce_n = ce; float av_n = av;
        if (inext < end) {
            int idn = inext + (lane >> 2);
            ce_n = (idn < end) ? g_csr[idn] : make_int2(node, 0);
            av_n = g_as1[ce_n.x * 4 + (lane & 3)];
        }
        float w8 = __expf(lrelu(av + adh, 0.2f));
        wsum += w8;
        int ss[8];
#pragma unroll
        for (int k = 0; k < 8; k++) ss[k] = __shfl_sync(0xffffffffu, ce.x, k * 4);
        float2 vv[8];
#pragma unroll
        for (int k = 0; k < 8; k++) vv[k] = h2f2(g_hp1h[ss[k] * 32 + lane]);
#pragma unroll
        for (int k = 0; k < 8; k++) {
            float wl = __shfl_sync(0xffffffffu, w8, k * 4 + (lane >> 3));
            acc.x = fmaf(wl, vv[k].x, acc.x);
            acc.y = fmaf(wl, vv[k].y, acc.y);
        }
        i = inext;
        ce = ce_n; av = av_n;
    }
    // padded tail strip (ce/av already prefetched with padding)
    if (i < end) {
        float w8 = (i + (lane >> 2) < end) ? __expf(lrelu(av + adh, 0.2f)) : 0.f;
        wsum += w8;
        int ss[8];
#pragma unroll
        for (int k = 0; k < 8; k++) ss[k] = __shfl_sync(0xffffffffu, ce.x, k * 4);
        float2 vv[8];
#pragma unroll
        for (int k = 0; k < 8; k++) vv[k] = h2f2(g_hp1h[ss[k] * 32 + lane]);
#pragma unroll
        for (int k = 0; k < 8; k++) {
            float wl = __shfl_sync(0xffffffffu, w8, k * 4 + (lane >> 3));
            acc.x = fmaf(wl, vv[k].x, acc.x);
            acc.y = fmaf(wl, vv[k].y, acc.y);
        }
    }
    *(float2*)&g_out1[node * 64 + lane * 2] = acc;
    wsum += __shfl_xor_sync(0xffffffffu, wsum, 4);
    wsum += __shfl_xor_sync(0xffffffffu, wsum, 8);
    wsum += __shfl_xor_sync(0xffffffffu, wsum, 16);
    if (lane < 4) g_asum1[node * 4 + lane] += wsum;
}

// ==================== kernel: finish gat1 + gat2 projection (FFMA2) ==========
__global__ void k_fin1_gat2(const float* __restrict__ g1b,
                            const float* __restrict__ g2W,
                            const float* __restrict__ g2as, const float* __restrict__ g2ad,
                            int n) {
    __shared__ __align__(16) float sW[64 * 64];
    __shared__ __align__(16) float sB[64], sAs[64], sAd[64];
    for (int i = threadIdx.x; i < 4096; i += blockDim.x) sW[i] = g2W[i];
    if (threadIdx.x < 64) {
        sB[threadIdx.x] = g1b[threadIdx.x];
        sAs[threadIdx.x] = g2as[threadIdx.x];
        sAd[threadIdx.x] = g2ad[threadIdx.x];
    }
    __syncthreads();
    int node = blockIdx.x * blockDim.x + threadIdx.x;
    if (node >= n) return;

    float inv[4];
#pragma unroll
    for (int h = 0; h < 4; h++) inv[h] = 1.0f / g_asum1[node * 4 + h];

    ull acc[32];
#pragma unroll
    for (int i = 0; i < 32; i++) acc[i] = 0ULL;
#pragma unroll 2
    for (int k4 = 0; k4 < 16; k4++) {
        float4 o = *(const float4*)&g_out1[node * 64 + k4 * 4];
        float iv = inv[k4 >> 2];
        float hv4[4];
        hv4[0] = o.x * iv + sB[k4 * 4];
        hv4[1] = o.y * iv + sB[k4 * 4 + 1];
        hv4[2] = o.z * iv + sB[k4 * 4 + 2];
        hv4[3] = o.w * iv + sB[k4 * 4 + 3];
#pragma unroll
        for (int j = 0; j < 4; j++) {
            float hj = hv4[j] > 0.f ? hv4[j] : expm1f(hv4[j]);
            ull hv = pack2(hj);
            const ulonglong2* wr = (const ulonglong2*)&sW[(k4 * 4 + j) * 64];
#pragma unroll
            for (int c8 = 0; c8 < 16; c8++) {
                ulonglong2 w = wr[c8];
                fma2(acc[2 * c8], hv, w.x);
                fma2(acc[2 * c8 + 1], hv, w.y);
            }
        }
    }
    float hp[64];
#pragma unroll
    for (int i = 0; i < 32; i++) {
        float2 f = unpack2(acc[i]);
        hp[2 * i] = f.x; hp[2 * i + 1] = f.y;
    }
    float as = 0.f, ad = 0.f;
#pragma unroll
    for (int c = 0; c < 64; c++) {
        as = fmaf(hp[c], sAs[c], as);
        ad = fmaf(hp[c], sAd[c], ad);
    }
    g_as2[node] = as;
    g_ad2[node] = ad;
    float es = __expf(lrelu(as + ad, 0.2f));
    g_asum2[node] = es;
#pragma unroll
    for (int q = 0; q < 8; q++) {
        int c = q * 8;
        uint4 u = make_uint4(h2bits(hp[c], hp[c + 1]), h2bits(hp[c + 2], hp[c + 3]),
                             h2bits(hp[c + 4], hp[c + 5]), h2bits(hp[c + 6], hp[c + 7]));
        *(uint4*)&g_hp2h[node * 32 + q * 4] = u;
        *(float4*)&g_out2[node * 64 + c] =
            make_float4(hp[c] * es, hp[c + 1] * es, hp[c + 2] * es, hp[c + 3] * es);
        *(float4*)&g_out2[node * 64 + c + 4] =
            make_float4(hp[c + 4] * es, hp[c + 5] * es, hp[c + 6] * es, hp[c + 7] * es);
    }
}

// ==================== kernel: gat2 gather (warp/node, pipelined) =============
__global__ void k_msg2(int n) {
    int warp = (blockIdx.x * blockDim.x + threadIdx.x) >> 5;
    if (warp >= n) return;
    int node = warp;
    int lane = threadIdx.x & 31;
    int beg = g_offs[node], end = g_offs[node + 1];

    float ad2 = g_ad2[node];
    float2 acc = *(const float2*)&g_out2[node * 64 + lane * 2];
    float wsum = 0.f;

    int i = beg;
    int idx0 = i + lane;
    int2 ce = (idx0 < end) ? g_csr[idx0] : make_int2(0, 0);
    float asv = g_as2[ce.x];

    // full 32-blocks
    for (; i + 32 <= end; ) {
        int inext = i + 32;
        int2 ce_n = ce; float as_n = asv;
        if (inext < end) {
            int idn = inext + lane;
            ce_n = (idn < end) ? g_csr[idn] : make_int2(0, 0);
            as_n = g_as2[ce_n.x];
        }
        float w32 = __expf(lrelu(asv + ad2, 0.2f));
        wsum += w32;
#pragma unroll
        for (int kk = 0; kk < 4; kk++) {
            int ss[8];
#pragma unroll
            for (int k = 0; k < 8; k++) ss[k] = __shfl_sync(0xffffffffu, ce.x, kk * 8 + k);
            float2 vv[8];
#pragma unroll
            for (int k = 0; k < 8; k++) vv[k] = h2f2(g_hp2h[ss[k] * 32 + lane]);
#pragma unroll
            for (int k = 0; k < 8; k++) {
                float wl = __shfl_sync(0xffffffffu, w32, kk * 8 + k);
                acc.x = fmaf(wl, vv[k].x, acc.x);
                acc.y = fmaf(wl, vv[k].y, acc.y);
            }
        }
        i = inext;
        ce = ce_n; asv = as_n;
    }
    // partial tail block (w = 0 padding makes garbage gathers harmless)
    if (i < end) {
        float w32 = (i + lane < end) ? __expf(lrelu(asv + ad2, 0.2f)) : 0.f;
        wsum += w32;
#pragma unroll
        for (int kk = 0; kk < 4; kk++) {
            if (i + kk * 8 >= end) break;
            int ss[8];
#pragma unroll
            for (int k = 0; k < 8; k++) ss[k] = __shfl_sync(0xffffffffu, ce.x, kk * 8 + k);
            float2 vv[8];
#pragma unroll
            for (int k = 0; k < 8; k++) vv[k] = h2f2(g_hp2h[ss[k] * 32 + lane]);
#pragma unroll
            for (int k = 0; k < 8; k++) {
                float wl = __shfl_sync(0xffffffffu, w32, kk * 8 + k);
                acc.x = fmaf(wl, vv[k].x, acc.x);
                acc.y = fmaf(wl, vv[k].y, acc.y);
            }
        }
    }
    *(float2*)&g_out2[node * 64 + lane * 2] = acc;
    wsum += __shfl_xor_sync(0xffffffffu, wsum, 16);
    wsum += __shfl_xor_sync(0xffffffffu, wsum, 8);
    wsum += __shfl_xor_sync(0xffffffffu, wsum, 4);
    wsum += __shfl_xor_sync(0xffffffffu, wsum, 2);
    wsum += __shfl_xor_sync(0xffffffffu, wsum, 1);
    if (lane == 0) g_asum2[node] += wsum;
}

// ==================== kernel: finish gat2 + EA/EB + node head (FFMA2) ========
__global__ void k_fin2_heads(const float* __restrict__ g2b,
                             const float* __restrict__ eoW1, const float* __restrict__ eob1,
                             const float* __restrict__ noW1, const float* __restrict__ nob1,
                             const float* __restrict__ noW2, const float* __restrict__ nob2,
                             float* __restrict__ out, int n, int e) {
    __shared__ __align__(16) float sWa[64 * 64];
    __shared__ __align__(16) float sWb[64 * 64];
    __shared__ __align__(16) float sWn[64 * 64];
    __shared__ __align__(16) float sB[64], sB1[64], sBn[64], sW2[128];
    for (int i = threadIdx.x; i < 4096; i += blockDim.x) {
        sWa[i] = eoW1[i];
        sWb[i] = eoW1[4096 + i];
        sWn[i] = noW1[i];
    }
    if (threadIdx.x < 64) {
        sB[threadIdx.x]  = g2b[threadIdx.x];
        sB1[threadIdx.x] = eob1[threadIdx.x];
        sBn[threadIdx.x] = nob1[threadIdx.x];
    }
    if (threadIdx.x < 128) sW2[threadIdx.x] = noW2[threadIdx.x];
    __syncthreads();
    int node = blockIdx.x * blockDim.x + threadIdx.x;
    if (node >= n) return;

    float inv = 1.0f / g_asum2[node];
    float h2[64];
#pragma unroll
    for (int c4 = 0; c4 < 16; c4++) {
        float4 o = *(const float4*)&g_out2[node * 64 + c4 * 4];
        h2[c4 * 4]     = o.x * inv + sB[c4 * 4];
        h2[c4 * 4 + 1] = o.y * inv + sB[c4 * 4 + 1];
        h2[c4 * 4 + 2] = o.z * inv + sB[c4 * 4 + 2];
        h2[c4 * 4 + 3] = o.w * inv + sB[c4 * 4 + 3];
    }

    ull acc[32];
    // ---- EA = h2 @ Wa + b1 (fp16 store) ----
#pragma unroll
    for (int i = 0; i < 32; i++) acc[i] = 0ULL;
#pragma unroll 4
    for (int k = 0; k < 64; k++) {
        ull hv = pack2(h2[k]);
        const ulonglong2* wr = (const ulonglong2*)&sWa[k * 64];
#pragma unroll
        for (int c8 = 0; c8 < 16; c8++) {
            ulonglong2 w = wr[c8];
            fma2(acc[2 * c8], hv, w.x);
            fma2(acc[2 * c8 + 1], hv, w.y);
        }
    }
#pragma unroll
    for (int q = 0; q < 8; q++) {
        float2 f0 = unpack2(acc[q * 4]),     f1 = unpack2(acc[q * 4 + 1]);
        float2 f2 = unpack2(acc[q * 4 + 2]), f3 = unpack2(acc[q * 4 + 3]);
        int c = q * 8;
        uint4 u = make_uint4(h2bits(f0.x + sB1[c], f0.y + sB1[c + 1]),
                             h2bits(f1.x + sB1[c + 2], f1.y + sB1[c + 3]),
                             h2bits(f2.x + sB1[c + 4], f2.y + sB1[c + 5]),
                             h2bits(f3.x + sB1[c + 6], f3.y + sB1[c + 7]));
        *(uint4*)&g_EAh[node * 32 + q * 4] = u;
    }
    // ---- EB = h2 @ Wb (fp32) ----
#pragma unroll
    for (int i = 0; i < 32; i++) acc[i] = 0ULL;
#pragma unroll 4
    for (int k = 0; k < 64; k++) {
        ull hv = pack2(h2[k]);
        const ulonglong2* wr = (const ulonglong2*)&sWb[k * 64];
#pragma unroll
        for (int c8 = 0; c8 < 16; c8++) {
            ulonglong2 w = wr[c8];
            fma2(acc[2 * c8], hv, w.x);
            fma2(acc[2 * c8 + 1], hv, w.y);
        }
    }
#pragma unroll
    for (int q = 0; q < 16; q++) {
        float2 f0 = unpack2(acc[q * 2]), f1 = unpack2(acc[q * 2 + 1]);
        *(float4*)&g_EB[node * 64 + q * 4] = make_float4(f0.x, f0.y, f1.x, f1.y);
    }
    // ---- node head ----
#pragma unroll
    for (int i = 0; i < 32; i++) acc[i] = 0ULL;
#pragma unroll 4
    for (int k = 0; k < 64; k++) {
        ull hv = pack2(h2[k]);
        const ulonglong2* wr = (const ulonglong2*)&sWn[k * 64];
#pragma unroll
        for (int c8 = 0; c8 < 16; c8++) {
            ulonglong2 w = wr[c8];
            fma2(acc[2 * c8], hv, w.x);
            fma2(acc[2 * c8 + 1], hv, w.y);
        }
    }
    float p0 = 0.f, p1 = 0.f;
#pragma unroll
    for (int i = 0; i < 32; i++) {
        float2 f = unpack2(acc[i]);
        float t0 = lrelu(f.x + sBn[2 * i], 0.01f);
        float t1 = lrelu(f.y + sBn[2 * i + 1], 0.01f);
        p0 = fmaf(t0, sW2[4 * i],     fmaf(t1, sW2[4 * i + 2], p0));
        p1 = fmaf(t0, sW2[4 * i + 1], fmaf(t1, sW2[4 * i + 3], p1));
    }
    out[e + node * 2]     = tanha(p0 + nob2[0]);
    out[e + node * 2 + 1] = tanha(p1 + nob2[1]);
}

// ==================== kernel: edge head (warp/node, pipelined) ===============
__global__ void k_edgehead(const float* __restrict__ eattr,
                           const float* __restrict__ eoW1,
                           const float* __restrict__ eoW2, const float* __restrict__ eob2,
                           float* __restrict__ out, int n) {
    int warp = (blockIdx.x * blockDim.x + threadIdx.x) >> 5;
    if (warp >= n) return;
    int node = warp;
    int lane = threadIdx.x & 31;
    int beg = g_offs[node], end = g_offs[node + 1];
    if (beg == end) return;

    float2 w128 = *(const float2*)&eoW1[128 * 64 + lane * 2];
    float2 w129 = *(const float2*)&eoW1[129 * 64 + lane * 2];
    float2 w2   = *(const float2*)&eoW2[lane * 2];
    float  b2   = eob2[0];
    float2 eb   = *(const float2*)&g_EB[node * 64 + lane * 2];

    int i = beg;
    int idx0 = i + lane;
    int2 ce = (idx0 < end) ? g_csr[idx0] : make_int2(0, 0);
    float2 ea = *(const float2*)&eattr[ce.y * 2];

    // full 32-blocks: no predicates, unconditional stores
    for (; i + 32 <= end; ) {
        int inext = i + 32;
        int2 ce_n = ce; float2 ea_n = ea;
        if (inext < end) {
            int idn = inext + lane;
            ce_n = (idn < end) ? g_csr[idn] : make_int2(0, 0);
            ea_n = *(const float2*)&eattr[ce_n.y * 2];
        }
#pragma unroll
        for (int kk = 0; kk < 4; kk++) {
            int ss[8], ei[8];
            float ex[8], ey[8];
#pragma unroll
            for (int k = 0; k < 8; k++) {
                ss[k] = __shfl_sync(0xffffffffu, ce.x, kk * 8 + k);
                ei[k] = __shfl_sync(0xffffffffu, ce.y, kk * 8 + k);
                ex[k] = __shfl_sync(0xffffffffu, ea.x, kk * 8 + k);
                ey[k] = __shfl_sync(0xffffffffu, ea.y, kk * 8 + k);
            }
            float2 va[8];
#pragma unroll
            for (int k = 0; k < 8; k++) va[k] = h2f2(g_EAh[ss[k] * 32 + lane]);
            float p[8];
#pragma unroll
            for (int k = 0; k < 8; k++) {
                float pre0 = va[k].x + eb.x + ex[k] * w128.x + ey[k] * w129.x;
                float pre1 = va[k].y + eb.y + ex[k] * w128.y + ey[k] * w129.y;
                p[k] = lrelu(pre0, 0.01f) * w2.x + lrelu(pre1, 0.01f) * w2.y;
            }
#pragma unroll
            for (int k = 0; k < 8; k++) {
                p[k] += __shfl_xor_sync(0xffffffffu, p[k], 16);
                p[k] += __shfl_xor_sync(0xffffffffu, p[k], 8);
                p[k] += __shfl_xor_sync(0xffffffffu, p[k], 4);
                p[k] += __shfl_xor_sync(0xffffffffu, p[k], 2);
                p[k] += __shfl_xor_sync(0xffffffffu, p[k], 1);
            }
            if (lane == 0) {
#pragma unroll
                for (int k = 0; k < 8; k++) out[ei[k]] = tanha(p[k] + b2);
            }
        }
        i = inext;
        ce = ce_n; ea = ea_n;
    }
    // partial tail block
    if (i < end) {
#pragma unroll
        for (int kk = 0; kk < 4; kk++) {
            if (i + kk * 8 >= end) break;
            int ss[8], ei[8];
            float ex[8], ey[8];
#pragma unroll
            for (int k = 0; k < 8; k++) {
                ss[k] = __shfl_sync(0xffffffffu, ce.x, kk * 8 + k);
                ei[k] = __shfl_sync(0xffffffffu, ce.y, kk * 8 + k);
                ex[k] = __shfl_sync(0xffffffffu, ea.x, kk * 8 + k);
                ey[k] = __shfl_sync(0xffffffffu, ea.y, kk * 8 + k);
            }
            float2 va[8];
#pragma unroll
            for (int k = 0; k < 8; k++) va[k] = h2f2(g_EAh[ss[k] * 32 + lane]);
            float p[8];
#pragma unroll
            for (int k = 0; k < 8; k++) {
                float pre0 = va[k].x + eb.x + ex[k] * w128.x + ey[k] * w129.x;
                float pre1 = va[k].y + eb.y + ex[k] * w128.y + ey[k] * w129.y;
                p[k] = lrelu(pre0, 0.01f) * w2.x + lrelu(pre1, 0.01f) * w2.y;
            }
#pragma unroll
            for (int k = 0; k < 8; k++) {
                p[k] += __shfl_xor_sync(0xffffffffu, p[k], 16);
                p[k] += __shfl_xor_sync(0xffffffffu, p[k], 8);
                p[k] += __shfl_xor_sync(0xffffffffu, p[k], 4);
                p[k] += __shfl_xor_sync(0xffffffffu, p[k], 2);
                p[k] += __shfl_xor_sync(0xffffffffu, p[k], 1);
            }
#pragma unroll
            for (int k = 0; k < 8; k++)
                if (lane == 0 && (i + kk * 8 + k) < end) out[ei[k]] = tanha(p[k] + b2);
        }
    }
}

// ==================== launch ==================================================
extern "C" void kernel_launch(void* const* d_in, const int* in_sizes, int n_in,
                              void* d_out, int out_size) {
    const float* x      = (const float*)d_in[0];
    const int*   eidx   = (const int*)d_in[1];
    const float* eattr  = (const float*)d_in[2];
    const float* encW   = (const float*)d_in[3];
    const float* encb   = (const float*)d_in[4];
    const float* g1W    = (const float*)d_in[5];
    const float* g1as   = (const float*)d_in[6];
    const float* g1ad   = (const float*)d_in[7];
    const float* g1b    = (const float*)d_in[8];
    const float* g2W    = (const float*)d_in[9];
    const float* g2as   = (const float*)d_in[10];
    const float* g2ad   = (const float*)d_in[11];
    const float* g2b    = (const float*)d_in[12];
    const float* noW1   = (const float*)d_in[13];
    const float* nob1   = (const float*)d_in[14];
    const float* noW2   = (const float*)d_in[15];
    const float* nob2   = (const float*)d_in[16];
    const float* eoW1   = (const float*)d_in[17];
    const float* eob1   = (const float*)d_in[18];
    const float* eoW2   = (const float*)d_in[19];
    const float* eob2   = (const float*)d_in[20];
    float* out = (float*)d_out;

    int n = in_sizes[0] / 2;
    int e = in_sizes[1] / 2;
    const int* src = eidx;
    const int* dst = eidx + e;

    const int B = 256;
    int gn = (n + B - 1) / B;
    int ge = (e + B - 1) / B;
    int gw = (n * 32 + B - 1) / B;

    // CSR build (dst-sorted) — g_cnt zero on entry, re-zeroed inside k_scanwrite
    k_hist<<<ge, B>>>(dst, e);
    k_sumscan<<<1, 1024>>>(n);
    k_scanwrite<<<NCHUNK, 1024>>>(n);
    k_scatter<<<ge, B>>>(src, dst, e);

    // pipeline
    k_enc_gat1<<<gn, B>>>(x, encW, encb, g1W, g1as, g1ad, n);
    k_msg1<<<gw, B>>>(n);
    k_fin1_gat2<<<gn, B>>>(g1b, g2W, g2as, g2ad, n);
    k_msg2<<<gw, B>>>(n);
    k_fin2_heads<<<gn, B>>>(g2b, eoW1, eob1, noW1, nob1, noW2, nob2, out, n, e);
    k_edgehead<<<gw, B>>>(eattr, eoW1, eoW2, eob2, out, n);
}